// round 2
// baseline (speedup 1.0000x reference)
#include <cuda_runtime.h>

#define N_NODES  100000
#define N_EDGES  600000
#define NODE_DIM 128
#define EDGE_DIM 16
#define OUT_DIM  128

// Scratch: Y[n][0:128] = x[n]@W_i + b, Y[n][128:256] = x[n]@W_j
__device__ __align__(16) float g_Y[(size_t)N_NODES * 256];

// ---------------------------------------------------------------------------
// GEMM: Y[m0+.., n0+..] tile. BM=64 rows, BN=128 cols, 256 threads, 4x8 micro.
// grid.x = 2 (col halves: n0=0 -> W_i(+bias), n0=128 -> W_j), grid.y = 1563.
// ---------------------------------------------------------------------------
__global__ void gemm_kernel(const float* __restrict__ x,
                            const float* __restrict__ W,
                            const float* __restrict__ b) {
    extern __shared__ float smem[];
    float* As = smem;               // [64][129] padded
    float* Ws = smem + 64 * 129;    // [128][128]

    const int n0  = blockIdx.x * 128;      // 0 or 128
    const int m0  = blockIdx.y * 64;
    const int tid = threadIdx.x;

    // Ws <- W rows [n0 .. n0+127], a contiguous 64KB block.
    {
        const float4* Wsrc = (const float4*)(W + (size_t)n0 * 128);
        float4* Wd = (float4*)Ws;
        #pragma unroll
        for (int p = 0; p < 16; p++) Wd[tid + p * 256] = Wsrc[tid + p * 256];
    }
    // As <- x[m0 .. m0+63][0:128], zero-fill past N_NODES.
    {
        const float4* x4 = (const float4*)x;
        #pragma unroll
        for (int p = 0; p < 8; p++) {
            int idx = tid + p * 256;
            int row = idx >> 5;
            int c4  = idx & 31;
            float4 v = make_float4(0.f, 0.f, 0.f, 0.f);
            if (m0 + row < N_NODES) v = x4[(size_t)(m0 + row) * 32 + c4];
            float* dst = As + row * 129 + c4 * 4;
            dst[0] = v.x; dst[1] = v.y; dst[2] = v.z; dst[3] = v.w;
        }
    }
    __syncthreads();

    const int tx = tid & 15;     // col group: cols tx*4 and 64+tx*4
    const int ty = tid >> 4;     // row group: rows ty*4 .. +3

    float4 acc0[4], acc1[4];
    {
        const float4 zero = make_float4(0.f, 0.f, 0.f, 0.f);
        const float4* b4 = (const float4*)b;
        float4 i0 = (n0 == 0) ? b4[tx]      : zero;
        float4 i1 = (n0 == 0) ? b4[16 + tx] : zero;
        #pragma unroll
        for (int i = 0; i < 4; i++) { acc0[i] = i0; acc1[i] = i1; }
    }

    const float*  Ar  = As + (ty * 4) * 129;
    const float4* Ws4 = (const float4*)Ws;

    #pragma unroll 8
    for (int k = 0; k < 128; k++) {
        float a[4];
        a[0] = Ar[k];
        a[1] = Ar[129 + k];
        a[2] = Ar[258 + k];
        a[3] = Ar[387 + k];
        float4 w0 = Ws4[k * 32 + tx];
        float4 w1 = Ws4[k * 32 + 16 + tx];
        #pragma unroll
        for (int i = 0; i < 4; i++) {
            acc0[i].x += a[i] * w0.x; acc0[i].y += a[i] * w0.y;
            acc0[i].z += a[i] * w0.z; acc0[i].w += a[i] * w0.w;
            acc1[i].x += a[i] * w1.x; acc1[i].y += a[i] * w1.y;
            acc1[i].z += a[i] * w1.z; acc1[i].w += a[i] * w1.w;
        }
    }

    #pragma unroll
    for (int i = 0; i < 4; i++) {
        int row = m0 + ty * 4 + i;
        if (row < N_NODES) {
            float4* o = (float4*)(g_Y + (size_t)row * 256 + n0);
            o[tx]      = acc0[i];
            o[16 + tx] = acc1[i];
        }
    }
}

// ---------------------------------------------------------------------------
// Edge kernel: 1 warp per edge, lane owns 4 contiguous output dims.
// out[e] = Y[src][0:128] + Y[dst][128:256] + edge_attr[e] @ W_e
// edge_index is INT32 (jax demotes int64 under default x64-disabled config).
// ---------------------------------------------------------------------------
__global__ void edge_kernel(const int* __restrict__ ei,
                            const float* __restrict__ edge_attr,
                            const float* __restrict__ W,
                            float* __restrict__ out) {
    __shared__ float We[EDGE_DIM * 128];   // 8 KB
    const int tid = threadIdx.x;
    {
        const float4* Wsrc = (const float4*)(W + (size_t)256 * 128);
        float4* Wd = (float4*)We;
        Wd[tid]       = Wsrc[tid];
        Wd[tid + 256] = Wsrc[tid + 256];
    }
    __syncthreads();

    const int e    = blockIdx.x * 8 + (tid >> 5);
    const int lane = tid & 31;

    const int s = ei[e];
    const int t = ei[N_EDGES + e];

    const float4* yi = (const float4*)(g_Y + (size_t)s * 256);
    const float4* yj = (const float4*)(g_Y + (size_t)t * 256 + 128);
    float4 va = yi[lane];
    float4 vb = yj[lane];
    float4 acc = make_float4(va.x + vb.x, va.y + vb.y, va.z + vb.z, va.w + vb.w);

    float ea[16];
    {
        const float4* ea4 = (const float4*)(edge_attr + (size_t)e * 16);
        #pragma unroll
        for (int q = 0; q < 4; q++) {
            float4 v = ea4[q];
            ea[4 * q]     = v.x;
            ea[4 * q + 1] = v.y;
            ea[4 * q + 2] = v.z;
            ea[4 * q + 3] = v.w;
        }
    }

    const float4* W4 = (const float4*)We;
    #pragma unroll
    for (int k = 0; k < 16; k++) {
        float4 w = W4[k * 32 + lane];
        acc.x += ea[k] * w.x;
        acc.y += ea[k] * w.y;
        acc.z += ea[k] * w.z;
        acc.w += ea[k] * w.w;
    }

    ((float4*)(out + (size_t)e * 128))[lane] = acc;
}

// ---------------------------------------------------------------------------
extern "C" void kernel_launch(void* const* d_in, const int* in_sizes, int n_in,
                              void* d_out, int out_size) {
    const float* x  = (const float*)d_in[0];
    const int*   ei = (const int*)d_in[1];
    const float* ea = (const float*)d_in[2];
    const float* W  = (const float*)d_in[3];
    const float* b  = (const float*)d_in[4];
    float* out = (float*)d_out;

    const size_t smem_bytes = (size_t)(64 * 129 + 128 * 128) * sizeof(float);
    cudaFuncSetAttribute(gemm_kernel,
                         cudaFuncAttributeMaxDynamicSharedMemorySize,
                         (int)smem_bytes);

    gemm_kernel<<<dim3(2, (N_NODES + 63) / 64), 256, smem_bytes>>>(x, W, b);
    edge_kernel<<<N_EDGES / 8, 256>>>(ei, ea, W, out);
}